// round 3
// baseline (speedup 1.0000x reference)
#include <cuda_runtime.h>
#include <math.h>

#define BATCH 8
#define CH 512
#define HWP 1024
#define NHEADS 8
#define HDIM 64
#define NPIX (BATCH*HWP)   // 8192

// Scratch (allocation-free rule: __device__ globals). 128B-aligned for float4.
__device__ alignas(128) float g_xn[(size_t)NPIX * CH];        // LN output, (B*HW, C)
__device__ alignas(128) float g_qkv[(size_t)NPIX * 3 * CH];   // (B*HW, 3C)
__device__ alignas(128) float g_attn[(size_t)NPIX * CH];      // attention output, (B*HW, C)

// ---------------------------------------------------------------------------
// Kernel 1: LayerNorm over channels. Block = one (b,h) row of 32 pixels.
// ---------------------------------------------------------------------------
__global__ __launch_bounds__(256) void ln_kernel(const float* __restrict__ x,
                                                 const float* __restrict__ ln_w,
                                                 const float* __restrict__ ln_b) {
    int b = blockIdx.x >> 5;
    int h = blockIdx.x & 31;
    int tid = threadIdx.x;
    int w = tid & 31;
    int cg = tid >> 5;  // 0..7

    __shared__ float s_sum[8][32];
    __shared__ float s_sq[8][32];
    __shared__ float s_mean[32];
    __shared__ float s_rstd[32];

    const float* xb = x + ((size_t)b * CH) * HWP + h * 32 + w;

    float sum = 0.f, sq = 0.f;
    for (int c = cg; c < CH; c += 8) {
        float v = xb[(size_t)c * HWP];
        sum += v; sq += v * v;
    }
    s_sum[cg][w] = sum;
    s_sq[cg][w] = sq;
    __syncthreads();
    if (cg == 0) {
        float ts = 0.f, tq = 0.f;
        #pragma unroll
        for (int g = 0; g < 8; g++) { ts += s_sum[g][w]; tq += s_sq[g][w]; }
        float mean = ts * (1.0f / CH);
        float var = tq * (1.0f / CH) - mean * mean;
        s_mean[w] = mean;
        s_rstd[w] = rsqrtf(var + 1e-5f);
    }
    __syncthreads();
    float mean = s_mean[w], rstd = s_rstd[w];
    float* outp = g_xn + ((size_t)b * HWP + h * 32 + w) * CH;
    for (int c = cg; c < CH; c += 8) {
        float v = xb[(size_t)c * HWP];
        outp[c] = (v - mean) * rstd * ln_w[c] + ln_b[c];
    }
}

// ---------------------------------------------------------------------------
// Kernel 2: QKV GEMM  C[8192,1536] = g_xn[8192,512] * qkv_w[1536,512]^T + b
// 128x128 tile, BK=16, 256 threads, 8x8 per thread (split 4+4 layout).
// ---------------------------------------------------------------------------
__global__ __launch_bounds__(256) void qkv_gemm(const float* __restrict__ Bw,
                                                const float* __restrict__ bias) {
    __shared__ float As[16][128];
    __shared__ float Bs[16][128];

    int tid = threadIdx.x;
    int tx = tid & 15;
    int ty = tid >> 4;
    int row0 = blockIdx.y * 128;
    int col0 = blockIdx.x * 128;

    int lr = tid >> 1;          // 0..127 tile row
    int lk = (tid & 1) * 8;     // 0 or 8

    const float* Ap = g_xn + (size_t)(row0 + lr) * CH + lk;
    const float* Bp = Bw + (size_t)(col0 + lr) * CH + lk;

    float acc[8][8];
    #pragma unroll
    for (int i = 0; i < 8; i++)
        #pragma unroll
        for (int j = 0; j < 8; j++) acc[i][j] = 0.f;

    for (int k0 = 0; k0 < CH; k0 += 16) {
        float4 a0 = *(const float4*)(Ap + k0);
        float4 a1 = *(const float4*)(Ap + k0 + 4);
        float4 b0 = *(const float4*)(Bp + k0);
        float4 b1 = *(const float4*)(Bp + k0 + 4);
        __syncthreads();
        As[lk + 0][lr] = a0.x; As[lk + 1][lr] = a0.y; As[lk + 2][lr] = a0.z; As[lk + 3][lr] = a0.w;
        As[lk + 4][lr] = a1.x; As[lk + 5][lr] = a1.y; As[lk + 6][lr] = a1.z; As[lk + 7][lr] = a1.w;
        Bs[lk + 0][lr] = b0.x; Bs[lk + 1][lr] = b0.y; Bs[lk + 2][lr] = b0.z; Bs[lk + 3][lr] = b0.w;
        Bs[lk + 4][lr] = b1.x; Bs[lk + 5][lr] = b1.y; Bs[lk + 6][lr] = b1.z; Bs[lk + 7][lr] = b1.w;
        __syncthreads();
        #pragma unroll
        for (int kk = 0; kk < 16; kk++) {
            float av[8], bv[8];
            *(float4*)&av[0] = *(const float4*)&As[kk][ty * 4];
            *(float4*)&av[4] = *(const float4*)&As[kk][64 + ty * 4];
            *(float4*)&bv[0] = *(const float4*)&Bs[kk][tx * 4];
            *(float4*)&bv[4] = *(const float4*)&Bs[kk][64 + tx * 4];
            #pragma unroll
            for (int i = 0; i < 8; i++)
                #pragma unroll
                for (int j = 0; j < 8; j++) acc[i][j] += av[i] * bv[j];
        }
    }

    #pragma unroll
    for (int i = 0; i < 8; i++) {
        int r = row0 + ((i < 4) ? (ty * 4 + i) : (60 + ty * 4 + i));
        float* orow = g_qkv + (size_t)r * (3 * CH);
        #pragma unroll
        for (int jh = 0; jh < 2; jh++) {
            int c = col0 + jh * 64 + tx * 4;
            float4 bb = *(const float4*)(bias + c);
            float4 o;
            o.x = acc[i][jh * 4 + 0] + bb.x;
            o.y = acc[i][jh * 4 + 1] + bb.y;
            o.z = acc[i][jh * 4 + 2] + bb.z;
            o.w = acc[i][jh * 4 + 3] + bb.w;
            *(float4*)(orow + c) = o;
        }
    }
}

// ---------------------------------------------------------------------------
// Kernel 3: Flash attention (fp32). Block = (qtile, head, b). Br=Bc=64.
// ---------------------------------------------------------------------------
__global__ __launch_bounds__(256) void attn_kernel() {
    __shared__ float Qs[64][64];   // [d][r]
    __shared__ float KPs[64][64];  // K phase: [d][c]; P phase: [r][c]
    __shared__ float Vs[64][64];   // [c][d]

    int tid = threadIdx.x;
    int tc = tid & 15;
    int tr = tid >> 4;
    int b = blockIdx.z;
    int head = blockIdx.y;
    int q0 = blockIdx.x * 64;

    const float* base = g_qkv + (size_t)b * HWP * (3 * CH) + head * HDIM;

    int lrow = tid >> 2;          // 0..63
    int ld0 = (tid & 3) * 16;     // d chunk base

    // Load Q tile transposed: Qs[d][r]
    {
        const float* qrow = base + (size_t)(q0 + lrow) * (3 * CH) + ld0;
        #pragma unroll
        for (int j = 0; j < 16; j += 4) {
            float4 v = *(const float4*)(qrow + j);
            Qs[ld0 + j + 0][lrow] = v.x;
            Qs[ld0 + j + 1][lrow] = v.y;
            Qs[ld0 + j + 2][lrow] = v.z;
            Qs[ld0 + j + 3][lrow] = v.w;
        }
    }

    float m_run[4], l_run[4], oA[4][4];
    #pragma unroll
    for (int i = 0; i < 4; i++) {
        m_run[i] = -INFINITY; l_run[i] = 0.f;
        #pragma unroll
        for (int j = 0; j < 4; j++) oA[i][j] = 0.f;
    }
    const float scale = 0.125f;  // 1/sqrt(64)

    for (int kt = 0; kt < 16; kt++) {
        int k0 = kt * 64;
        __syncthreads();  // previous iteration's P/V reads complete
        // Load K tile transposed [d][c] and V tile [c][d]
        {
            const float* krow = base + CH + (size_t)(k0 + lrow) * (3 * CH) + ld0;
            const float* vrow = base + 2 * CH + (size_t)(k0 + lrow) * (3 * CH) + ld0;
            #pragma unroll
            for (int j = 0; j < 16; j += 4) {
                float4 kv = *(const float4*)(krow + j);
                KPs[ld0 + j + 0][lrow] = kv.x;
                KPs[ld0 + j + 1][lrow] = kv.y;
                KPs[ld0 + j + 2][lrow] = kv.z;
                KPs[ld0 + j + 3][lrow] = kv.w;
                *(float4*)&Vs[lrow][ld0 + j] = *(const float4*)(vrow + j);
            }
        }
        __syncthreads();

        // S = scale * Q K^T  (4x4 per thread)
        float s[4][4];
        #pragma unroll
        for (int i = 0; i < 4; i++)
            #pragma unroll
            for (int j = 0; j < 4; j++) s[i][j] = 0.f;
        #pragma unroll 16
        for (int d = 0; d < 64; d++) {
            float4 qa = *(const float4*)&Qs[d][tr * 4];
            float4 kb = *(const float4*)&KPs[d][tc * 4];
            float qv[4] = {qa.x, qa.y, qa.z, qa.w};
            float kv[4] = {kb.x, kb.y, kb.z, kb.w};
            #pragma unroll
            for (int i = 0; i < 4; i++)
                #pragma unroll
                for (int j = 0; j < 4; j++) s[i][j] += qv[i] * kv[j];
        }

        // Online softmax update
        float p[4][4];
        #pragma unroll
        for (int i = 0; i < 4; i++) {
            #pragma unroll
            for (int j = 0; j < 4; j++) s[i][j] *= scale;
            float mt = fmaxf(fmaxf(s[i][0], s[i][1]), fmaxf(s[i][2], s[i][3]));
            #pragma unroll
            for (int off = 8; off >= 1; off >>= 1)
                mt = fmaxf(mt, __shfl_xor_sync(0xffffffffu, mt, off, 16));
            float m_new = fmaxf(m_run[i], mt);
            float alpha = __expf(m_run[i] - m_new);
            float lt = 0.f;
            #pragma unroll
            for (int j = 0; j < 4; j++) {
                p[i][j] = __expf(s[i][j] - m_new);
                lt += p[i][j];
            }
            #pragma unroll
            for (int off = 8; off >= 1; off >>= 1)
                lt += __shfl_xor_sync(0xffffffffu, lt, off, 16);
            l_run[i] = l_run[i] * alpha + lt;
            m_run[i] = m_new;
            #pragma unroll
            for (int j = 0; j < 4; j++) oA[i][j] *= alpha;
        }

        __syncthreads();  // all S-reads of K done; reuse buffer for P
        #pragma unroll
        for (int i = 0; i < 4; i++)
            *(float4*)&KPs[tr * 4 + i][tc * 4] =
                make_float4(p[i][0], p[i][1], p[i][2], p[i][3]);
        __syncthreads();

        // O += P V
        #pragma unroll 16
        for (int c = 0; c < 64; c++) {
            float4 vv = *(const float4*)&Vs[c][tc * 4];
            float pv[4] = {vv.x, vv.y, vv.z, vv.w};
            #pragma unroll
            for (int i = 0; i < 4; i++) {
                float pr = KPs[tr * 4 + i][c];
                #pragma unroll
                for (int j = 0; j < 4; j++) oA[i][j] += pr * pv[j];
            }
        }
    }

    // Normalize and write (B*HW, C) with c = head*64 + d
    #pragma unroll
    for (int i = 0; i < 4; i++) {
        float inv = 1.0f / l_run[i];
        float4 o = make_float4(oA[i][0] * inv, oA[i][1] * inv,
                               oA[i][2] * inv, oA[i][3] * inv);
        size_t gi = ((size_t)b * HWP + q0 + tr * 4 + i) * CH + head * HDIM + tc * 4;
        *(float4*)(g_attn + gi) = o;
    }
}

// ---------------------------------------------------------------------------
// Kernel 4: Proj GEMM + bias + residual, output NCHW via smem transpose.
// ---------------------------------------------------------------------------
__global__ __launch_bounds__(256) void proj_gemm(const float* __restrict__ Bw,
                                                 const float* __restrict__ bias,
                                                 const float* __restrict__ x,
                                                 float* __restrict__ out) {
    __shared__ float smem[128 * 65];  // union: mainloop As/Bs (4096f) | epilogue Cs
    float (*As)[128] = (float (*)[128])smem;
    float (*Bs)[128] = (float (*)[128])(smem + 16 * 128);
    float (*Cs)[65] = (float (*)[65])smem;  // stride 65: scalar writes only!

    int tid = threadIdx.x;
    int tx = tid & 15;
    int ty = tid >> 4;
    int row0 = blockIdx.y * 128;
    int col0 = blockIdx.x * 128;

    int lr = tid >> 1;
    int lk = (tid & 1) * 8;

    const float* Ap = g_attn + (size_t)(row0 + lr) * CH + lk;
    const float* Bp = Bw + (size_t)(col0 + lr) * CH + lk;

    float acc[8][8];
    #pragma unroll
    for (int i = 0; i < 8; i++)
        #pragma unroll
        for (int j = 0; j < 8; j++) acc[i][j] = 0.f;

    for (int k0 = 0; k0 < CH; k0 += 16) {
        float4 a0 = *(const float4*)(Ap + k0);
        float4 a1 = *(const float4*)(Ap + k0 + 4);
        float4 b0 = *(const float4*)(Bp + k0);
        float4 b1 = *(const float4*)(Bp + k0 + 4);
        __syncthreads();
        As[lk + 0][lr] = a0.x; As[lk + 1][lr] = a0.y; As[lk + 2][lr] = a0.z; As[lk + 3][lr] = a0.w;
        As[lk + 4][lr] = a1.x; As[lk + 5][lr] = a1.y; As[lk + 6][lr] = a1.z; As[lk + 7][lr] = a1.w;
        Bs[lk + 0][lr] = b0.x; Bs[lk + 1][lr] = b0.y; Bs[lk + 2][lr] = b0.z; Bs[lk + 3][lr] = b0.w;
        Bs[lk + 4][lr] = b1.x; Bs[lk + 5][lr] = b1.y; Bs[lk + 6][lr] = b1.z; Bs[lk + 7][lr] = b1.w;
        __syncthreads();
        #pragma unroll
        for (int kk = 0; kk < 16; kk++) {
            float av[8], bv[8];
            *(float4*)&av[0] = *(const float4*)&As[kk][ty * 4];
            *(float4*)&av[4] = *(const float4*)&As[kk][64 + ty * 4];
            *(float4*)&bv[0] = *(const float4*)&Bs[kk][tx * 4];
            *(float4*)&bv[4] = *(const float4*)&Bs[kk][64 + tx * 4];
            #pragma unroll
            for (int i = 0; i < 8; i++)
                #pragma unroll
                for (int j = 0; j < 8; j++) acc[i][j] += av[i] * bv[j];
        }
    }

    // Epilogue: transpose through smem (scalar stores — stride-65 rows are not
    // 16B aligned), then coalesced NCHW writes with bias + residual.
    int b = row0 >> 10;
    int pixbase = row0 & 1023;
    #pragma unroll
    for (int h = 0; h < 2; h++) {
        __syncthreads();
        #pragma unroll
        for (int i = 0; i < 8; i++) {
            int rl = (i < 4) ? (ty * 4 + i) : (60 + ty * 4 + i);
            Cs[rl][tx * 4 + 0] = acc[i][h * 4 + 0];
            Cs[rl][tx * 4 + 1] = acc[i][h * 4 + 1];
            Cs[rl][tx * 4 + 2] = acc[i][h * 4 + 2];
            Cs[rl][tx * 4 + 3] = acc[i][h * 4 + 3];
        }
        __syncthreads();
        for (int idx = tid; idx < 64 * 128; idx += 256) {
            int ol = idx >> 7;       // 0..63 local output channel
            int p = idx & 127;       // 0..127 local pixel
            int o = col0 + h * 64 + ol;
            size_t gi = ((size_t)b * CH + o) * HWP + pixbase + p;
            out[gi] = Cs[p][ol] + bias[o] + x[gi];
        }
    }
}

// ---------------------------------------------------------------------------
extern "C" void kernel_launch(void* const* d_in, const int* in_sizes, int n_in,
                              void* d_out, int out_size) {
    const float* x      = (const float*)d_in[0];
    const float* ln_w   = (const float*)d_in[1];
    const float* ln_b   = (const float*)d_in[2];
    const float* qkv_w  = (const float*)d_in[3];
    const float* qkv_b  = (const float*)d_in[4];
    const float* proj_w = (const float*)d_in[5];
    const float* proj_b = (const float*)d_in[6];
    float* out = (float*)d_out;

    ln_kernel<<<BATCH * 32, 256>>>(x, ln_w, ln_b);
    qkv_gemm<<<dim3(12, 64), 256>>>(qkv_w, qkv_b);
    attn_kernel<<<dim3(16, NHEADS, BATCH), 256>>>();
    proj_gemm<<<dim3(4, 64), 256>>>(proj_w, proj_b, x, out);
}

// round 5
// speedup vs baseline: 2.1960x; 2.1960x over previous
#include <cuda_runtime.h>
#include <math.h>
#include <stdint.h>

#define BATCH 8
#define CH 512
#define HWP 1024
#define NHEADS 8
#define HDIM 64
#define NPIX (BATCH*HWP)   // 8192

// Scratch (allocation-free rule: __device__ globals). 128B-aligned.
__device__ alignas(128) float g_xn[(size_t)NPIX * CH];        // LN output, (B*HW, C)
__device__ alignas(128) float g_qkv[(size_t)NPIX * 3 * CH];   // (B*HW, 3C)
__device__ alignas(128) float g_attn[(size_t)NPIX * CH];      // attention output, (B*HW, C)

// ---------------------------------------------------------------------------
// Helpers: tf32 round + m16n8k8 tf32 mma
// ---------------------------------------------------------------------------
__device__ __forceinline__ float tf32r(float x) {
    uint32_t r;
    asm("cvt.rna.tf32.f32 %0, %1;" : "=r"(r) : "f"(x));
    return __uint_as_float(r);
}
__device__ __forceinline__ uint32_t tf32u(float x) {
    uint32_t r;
    asm("cvt.rna.tf32.f32 %0, %1;" : "=r"(r) : "f"(x));
    return r;
}
__device__ __forceinline__ void mma_tf32(float* c, uint32_t a0, uint32_t a1,
                                         uint32_t a2, uint32_t a3,
                                         uint32_t b0, uint32_t b1) {
    asm volatile(
        "mma.sync.aligned.m16n8k8.row.col.f32.tf32.tf32.f32 "
        "{%0,%1,%2,%3}, {%4,%5,%6,%7}, {%8,%9}, {%0,%1,%2,%3};"
        : "+f"(c[0]), "+f"(c[1]), "+f"(c[2]), "+f"(c[3])
        : "r"(a0), "r"(a1), "r"(a2), "r"(a3), "r"(b0), "r"(b1));
}

// ---------------------------------------------------------------------------
// Kernel 1: LayerNorm over channels. Block = one (b,h) row of 32 pixels.
// ---------------------------------------------------------------------------
__global__ __launch_bounds__(256) void ln_kernel(const float* __restrict__ x,
                                                 const float* __restrict__ ln_w,
                                                 const float* __restrict__ ln_b) {
    int b = blockIdx.x >> 5;
    int h = blockIdx.x & 31;
    int tid = threadIdx.x;
    int w = tid & 31;
    int cg = tid >> 5;  // 0..7

    __shared__ float s_sum[8][32];
    __shared__ float s_sq[8][32];
    __shared__ float s_mean[32];
    __shared__ float s_rstd[32];

    const float* xb = x + ((size_t)b * CH) * HWP + h * 32 + w;

    float sum = 0.f, sq = 0.f;
    for (int c = cg; c < CH; c += 8) {
        float v = xb[(size_t)c * HWP];
        sum += v; sq += v * v;
    }
    s_sum[cg][w] = sum;
    s_sq[cg][w] = sq;
    __syncthreads();
    if (cg == 0) {
        float ts = 0.f, tq = 0.f;
        #pragma unroll
        for (int g = 0; g < 8; g++) { ts += s_sum[g][w]; tq += s_sq[g][w]; }
        float mean = ts * (1.0f / CH);
        float var = tq * (1.0f / CH) - mean * mean;
        s_mean[w] = mean;
        s_rstd[w] = rsqrtf(var + 1e-5f);
    }
    __syncthreads();
    float mean = s_mean[w], rstd = s_rstd[w];
    float* outp = g_xn + ((size_t)b * HWP + h * 32 + w) * CH;
    for (int c = cg; c < CH; c += 8) {
        float v = xb[(size_t)c * HWP];
        outp[c] = (v - mean) * rstd * ln_w[c] + ln_b[c];
    }
}

// ---------------------------------------------------------------------------
// Kernel 2: QKV GEMM (tf32 mma). C[8192,1536] = g_xn[8192,512]·W[1536,512]^T + b
// Block 128x128, BK=32, 256 threads = 8 warps (4 m x 2 n). Warp tile 32x64.
// smem stride 36 -> fragment LDS banks 4g+t, conflict-free.
// ---------------------------------------------------------------------------
#define PADK 36
__global__ __launch_bounds__(256) void qkv_gemm(const float* __restrict__ Bw,
                                                const float* __restrict__ bias) {
    __shared__ float As[128][PADK];
    __shared__ float Bs[128][PADK];

    int tid = threadIdx.x;
    int wid = tid >> 5, lane = tid & 31;
    int wm = wid >> 1, wn = wid & 1;
    int g = lane >> 2, t = lane & 3;
    int row0 = blockIdx.y * 128, col0 = blockIdx.x * 128;

    int lr = tid >> 1;
    int lp = (tid & 1) * 16;
    const float* Ap = g_xn + (size_t)(row0 + lr) * CH + lp;
    const float* Bp = Bw + (size_t)(col0 + lr) * CH + lp;

    float acc[2][8][4];
    #pragma unroll
    for (int mt = 0; mt < 2; mt++)
        #pragma unroll
        for (int nt = 0; nt < 8; nt++)
            #pragma unroll
            for (int j = 0; j < 4; j++) acc[mt][nt][j] = 0.f;

    for (int k0 = 0; k0 < CH; k0 += 32) {
        float4 av[4], bv[4];
        #pragma unroll
        for (int i = 0; i < 4; i++) {
            av[i] = *(const float4*)(Ap + k0 + i * 4);
            bv[i] = *(const float4*)(Bp + k0 + i * 4);
        }
        __syncthreads();
        #pragma unroll
        for (int i = 0; i < 4; i++) {
            As[lr][lp + i * 4 + 0] = tf32r(av[i].x);
            As[lr][lp + i * 4 + 1] = tf32r(av[i].y);
            As[lr][lp + i * 4 + 2] = tf32r(av[i].z);
            As[lr][lp + i * 4 + 3] = tf32r(av[i].w);
            Bs[lr][lp + i * 4 + 0] = tf32r(bv[i].x);
            Bs[lr][lp + i * 4 + 1] = tf32r(bv[i].y);
            Bs[lr][lp + i * 4 + 2] = tf32r(bv[i].z);
            Bs[lr][lp + i * 4 + 3] = tf32r(bv[i].w);
        }
        __syncthreads();
        #pragma unroll
        for (int ks = 0; ks < 4; ks++) {
            int kk = ks * 8;
            uint32_t a[2][4];
            #pragma unroll
            for (int mt = 0; mt < 2; mt++) {
                int r = wm * 32 + mt * 16;
                a[mt][0] = __float_as_uint(As[r + g][kk + t]);
                a[mt][1] = __float_as_uint(As[r + g + 8][kk + t]);
                a[mt][2] = __float_as_uint(As[r + g][kk + t + 4]);
                a[mt][3] = __float_as_uint(As[r + g + 8][kk + t + 4]);
            }
            #pragma unroll
            for (int nt = 0; nt < 8; nt++) {
                int c = wn * 64 + nt * 8;
                uint32_t b0 = __float_as_uint(Bs[c + g][kk + t]);
                uint32_t b1 = __float_as_uint(Bs[c + g][kk + t + 4]);
                #pragma unroll
                for (int mt = 0; mt < 2; mt++)
                    mma_tf32(acc[mt][nt], a[mt][0], a[mt][1], a[mt][2], a[mt][3], b0, b1);
            }
        }
    }

    #pragma unroll
    for (int mt = 0; mt < 2; mt++) {
        int r = row0 + wm * 32 + mt * 16 + g;
        #pragma unroll
        for (int nt = 0; nt < 8; nt++) {
            int c = col0 + wn * 64 + nt * 8 + 2 * t;
            float bx = bias[c], by = bias[c + 1];
            *(float2*)(g_qkv + (size_t)r * (3 * CH) + c) =
                make_float2(acc[mt][nt][0] + bx, acc[mt][nt][1] + by);
            *(float2*)(g_qkv + (size_t)(r + 8) * (3 * CH) + c) =
                make_float2(acc[mt][nt][2] + bx, acc[mt][nt][3] + by);
        }
    }
}

// ---------------------------------------------------------------------------
// Kernel 3: Flash attention, tf32 mma for S=QK^T and O+=PV.
// Block = (qtile64, head, b), 128 threads = 4 warps, warp = 16 query rows.
// Q fragments hoisted to registers; smem = Ks[64][68] + Vt[64][68] (34.8KB).
// P C-frag -> A-frag conversion via warp shuffles (no smem round trip).
// ---------------------------------------------------------------------------
#define PADA 68
__global__ __launch_bounds__(128) void attn_kernel() {
    __shared__ float Ks[64][PADA];
    __shared__ float Vt[64][PADA];   // [d][c]

    int tid = threadIdx.x;
    int wid = tid >> 5, lane = tid & 31;
    int g = lane >> 2, t = lane & 3;
    int b = blockIdx.z, head = blockIdx.y;
    int q0 = blockIdx.x * 64;
    int m0 = wid * 16;

    const float* base = g_qkv + (size_t)b * HWP * (3 * CH) + head * HDIM;

    int lrow = tid >> 1;           // 0..63
    int lhalf = (tid & 1) * 32;    // col half

    // Stage Q into Ks, pull fragments to registers.
    {
        const float* qrow = base + (size_t)(q0 + lrow) * (3 * CH) + lhalf;
        #pragma unroll
        for (int j = 0; j < 32; j += 4) {
            float4 v = *(const float4*)(qrow + j);
            Ks[lrow][lhalf + j + 0] = tf32r(v.x);
            Ks[lrow][lhalf + j + 1] = tf32r(v.y);
            Ks[lrow][lhalf + j + 2] = tf32r(v.z);
            Ks[lrow][lhalf + j + 3] = tf32r(v.w);
        }
    }
    __syncthreads();
    uint32_t qf[8][4];
    #pragma unroll
    for (int ks = 0; ks < 8; ks++) {
        int kk = ks * 8;
        qf[ks][0] = __float_as_uint(Ks[m0 + g][kk + t]);
        qf[ks][1] = __float_as_uint(Ks[m0 + g + 8][kk + t]);
        qf[ks][2] = __float_as_uint(Ks[m0 + g][kk + t + 4]);
        qf[ks][3] = __float_as_uint(Ks[m0 + g + 8][kk + t + 4]);
    }

    float oA[8][4];
    #pragma unroll
    for (int nt = 0; nt < 8; nt++)
        #pragma unroll
        for (int j = 0; j < 4; j++) oA[nt][j] = 0.f;
    float m_run0 = -INFINITY, m_run1 = -INFINITY, l0 = 0.f, l1 = 0.f;
    const float scale = 0.125f;

    for (int kt = 0; kt < 16; kt++) {
        int k0 = kt * 64;
        const float* krow = base + CH + (size_t)(k0 + lrow) * (3 * CH) + lhalf;
        const float* vrow = base + 2 * CH + (size_t)(k0 + lrow) * (3 * CH) + lhalf;

        // pass 1: first 16 cols of this thread's half
        float4 kb[4], vb[4];
        #pragma unroll
        for (int i = 0; i < 4; i++) { kb[i] = *(const float4*)(krow + i * 4);
                                      vb[i] = *(const float4*)(vrow + i * 4); }
        __syncthreads();   // prior iteration's mma reads complete
        #pragma unroll
        for (int i = 0; i < 4; i++) {
            int c0 = lhalf + i * 4;
            Ks[lrow][c0 + 0] = tf32r(kb[i].x); Ks[lrow][c0 + 1] = tf32r(kb[i].y);
            Ks[lrow][c0 + 2] = tf32r(kb[i].z); Ks[lrow][c0 + 3] = tf32r(kb[i].w);
            Vt[c0 + 0][lrow] = tf32r(vb[i].x); Vt[c0 + 1][lrow] = tf32r(vb[i].y);
            Vt[c0 + 2][lrow] = tf32r(vb[i].z); Vt[c0 + 3][lrow] = tf32r(vb[i].w);
        }
        // pass 2: remaining 16 cols
        #pragma unroll
        for (int i = 0; i < 4; i++) { kb[i] = *(const float4*)(krow + 16 + i * 4);
                                      vb[i] = *(const float4*)(vrow + 16 + i * 4); }
        #pragma unroll
        for (int i = 0; i < 4; i++) {
            int c0 = lhalf + 16 + i * 4;
            Ks[lrow][c0 + 0] = tf32r(kb[i].x); Ks[lrow][c0 + 1] = tf32r(kb[i].y);
            Ks[lrow][c0 + 2] = tf32r(kb[i].z); Ks[lrow][c0 + 3] = tf32r(kb[i].w);
            Vt[c0 + 0][lrow] = tf32r(vb[i].x); Vt[c0 + 1][lrow] = tf32r(vb[i].y);
            Vt[c0 + 2][lrow] = tf32r(vb[i].z); Vt[c0 + 3][lrow] = tf32r(vb[i].w);
        }
        __syncthreads();

        // S = Q K^T
        float s[8][4];
        #pragma unroll
        for (int nt = 0; nt < 8; nt++) {
            s[nt][0] = s[nt][1] = s[nt][2] = s[nt][3] = 0.f;
            #pragma unroll
            for (int ks = 0; ks < 8; ks++) {
                uint32_t b0 = __float_as_uint(Ks[nt * 8 + g][ks * 8 + t]);
                uint32_t b1 = __float_as_uint(Ks[nt * 8 + g][ks * 8 + t + 4]);
                mma_tf32(s[nt], qf[ks][0], qf[ks][1], qf[ks][2], qf[ks][3], b0, b1);
            }
        }

        // Online softmax (rows g and g+8 per thread; full row across quad lanes)
        float sm0 = -INFINITY, sm1 = -INFINITY;
        #pragma unroll
        for (int nt = 0; nt < 8; nt++) {
            s[nt][0] *= scale; s[nt][1] *= scale; s[nt][2] *= scale; s[nt][3] *= scale;
            sm0 = fmaxf(sm0, fmaxf(s[nt][0], s[nt][1]));
            sm1 = fmaxf(sm1, fmaxf(s[nt][2], s[nt][3]));
        }
        sm0 = fmaxf(sm0, __shfl_xor_sync(0xffffffffu, sm0, 1));
        sm0 = fmaxf(sm0, __shfl_xor_sync(0xffffffffu, sm0, 2));
        sm1 = fmaxf(sm1, __shfl_xor_sync(0xffffffffu, sm1, 1));
        sm1 = fmaxf(sm1, __shfl_xor_sync(0xffffffffu, sm1, 2));
        float mn0 = fmaxf(m_run0, sm0), mn1 = fmaxf(m_run1, sm1);
        float al0 = __expf(m_run0 - mn0), al1 = __expf(m_run1 - mn1);
        float ls0 = 0.f, ls1 = 0.f;
        uint32_t pu[8][4];
        #pragma unroll
        for (int nt = 0; nt < 8; nt++) {
            float p0 = __expf(s[nt][0] - mn0);
            float p1 = __expf(s[nt][1] - mn0);
            float p2 = __expf(s[nt][2] - mn1);
            float p3 = __expf(s[nt][3] - mn1);
            ls0 += p0 + p1; ls1 += p2 + p3;
            pu[nt][0] = tf32u(p0); pu[nt][1] = tf32u(p1);
            pu[nt][2] = tf32u(p2); pu[nt][3] = tf32u(p3);
        }
        ls0 += __shfl_xor_sync(0xffffffffu, ls0, 1);
        ls0 += __shfl_xor_sync(0xffffffffu, ls0, 2);
        ls1 += __shfl_xor_sync(0xffffffffu, ls1, 1);
        ls1 += __shfl_xor_sync(0xffffffffu, ls1, 2);
        l0 = l0 * al0 + ls0; l1 = l1 * al1 + ls1;
        m_run0 = mn0; m_run1 = mn1;
        #pragma unroll
        for (int nt = 0; nt < 8; nt++) {
            oA[nt][0] *= al0; oA[nt][1] *= al0;
            oA[nt][2] *= al1; oA[nt][3] *= al1;
        }

        // O += P V.  P C-frag -> A-frag via shuffles: col c held by lane g*4+(c>>1),
        // reg c&1. A-frag wants cols t and t+4.
        int srcA = g * 4 + (t >> 1);
        int srcB = srcA + 2;
        bool odd = (t & 1);
        #pragma unroll
        for (int ks = 0; ks < 8; ks++) {
            uint32_t x0 = __shfl_sync(0xffffffffu, pu[ks][0], srcA);
            uint32_t x1 = __shfl_sync(0xffffffffu, pu[ks][1], srcA);
            uint32_t a0 = odd ? x1 : x0;
            uint32_t y0 = __shfl_sync(0xffffffffu, pu[ks][0], srcB);
            uint32_t y1 = __shfl_sync(0xffffffffu, pu[ks][1], srcB);
            uint32_t a2 = odd ? y1 : y0;
            x0 = __shfl_sync(0xffffffffu, pu[ks][2], srcA);
            x1 = __shfl_sync(0xffffffffu, pu[ks][3], srcA);
            uint32_t a1 = odd ? x1 : x0;
            y0 = __shfl_sync(0xffffffffu, pu[ks][2], srcB);
            y1 = __shfl_sync(0xffffffffu, pu[ks][3], srcB);
            uint32_t a3 = odd ? y1 : y0;
            #pragma unroll
            for (int nt = 0; nt < 8; nt++) {
                uint32_t b0 = __float_as_uint(Vt[nt * 8 + g][ks * 8 + t]);
                uint32_t b1 = __float_as_uint(Vt[nt * 8 + g][ks * 8 + t + 4]);
                mma_tf32(oA[nt], a0, a1, a2, a3, b0, b1);
            }
        }
    }

    // Normalize + write (B*HW, C), c = head*64 + nt*8 + 2t
    float inv0 = 1.0f / l0, inv1 = 1.0f / l1;
    size_t r0 = (size_t)b * HWP + q0 + m0 + g;
    #pragma unroll
    for (int nt = 0; nt < 8; nt++) {
        int c = head * HDIM + nt * 8 + 2 * t;
        *(float2*)(g_attn + r0 * CH + c) =
            make_float2(oA[nt][0] * inv0, oA[nt][1] * inv0);
        *(float2*)(g_attn + (r0 + 8) * CH + c) =
            make_float2(oA[nt][2] * inv1, oA[nt][3] * inv1);
    }
}

// ---------------------------------------------------------------------------
// Kernel 4: Proj GEMM (tf32 mma) + bias + residual, NCHW out via smem transpose.
// ---------------------------------------------------------------------------
__global__ __launch_bounds__(256) void proj_gemm(const float* __restrict__ Bw,
                                                 const float* __restrict__ bias,
                                                 const float* __restrict__ x,
                                                 float* __restrict__ out) {
    __shared__ float smem[128 * PADK * 2];   // 9216 floats
    float (*As)[PADK] = (float (*)[PADK])smem;
    float (*Bs)[PADK] = (float (*)[PADK])(smem + 128 * PADK);
    float (*Cs)[65] = (float (*)[65])smem;   // epilogue alias (8320 floats)

    int tid = threadIdx.x;
    int wid = tid >> 5, lane = tid & 31;
    int wm = wid >> 1, wn = wid & 1;
    int g = lane >> 2, t = lane & 3;
    int row0 = blockIdx.y * 128, col0 = blockIdx.x * 128;

    int lr = tid >> 1;
    int lp = (tid & 1) * 16;
    const float* Ap = g_attn + (size_t)(row0 + lr) * CH + lp;
    const float* Bp = Bw + (size_t)(col0 + lr) * CH + lp;

    float acc[2][8][4];
    #pragma unroll
    for (int mt = 0; mt < 2; mt++)
        #pragma unroll
        for (int nt = 0; nt < 8; nt++)
            #pragma unroll
            for (int j = 0; j < 4; j++) acc[mt][nt][j] = 0.f;

    for (int k0 = 0; k0 < CH; k0 += 32) {
        float4 av[4], bv[4];
        #pragma unroll
        for (int i = 0; i < 4; i++) {
            av[i] = *(const float4*)(Ap + k0 + i * 4);
            bv[i] = *(const float4*)(Bp + k0 + i * 4);
        }
        __syncthreads();
        #pragma unroll
        for (int i = 0; i < 4; i++) {
            As[lr][lp + i * 4 + 0] = tf32r(av[i].x);
            As[lr][lp + i * 4 + 1] = tf32r(av[i].y);
            As[lr][lp + i * 4 + 2] = tf32r(av[i].z);
            As[lr][lp + i * 4 + 3] = tf32r(av[i].w);
            Bs[lr][lp + i * 4 + 0] = tf32r(bv[i].x);
            Bs[lr][lp + i * 4 + 1] = tf32r(bv[i].y);
            Bs[lr][lp + i * 4 + 2] = tf32r(bv[i].z);
            Bs[lr][lp + i * 4 + 3] = tf32r(bv[i].w);
        }
        __syncthreads();
        #pragma unroll
        for (int ks = 0; ks < 4; ks++) {
            int kk = ks * 8;
            uint32_t a[2][4];
            #pragma unroll
            for (int mt = 0; mt < 2; mt++) {
                int r = wm * 32 + mt * 16;
                a[mt][0] = __float_as_uint(As[r + g][kk + t]);
                a[mt][1] = __float_as_uint(As[r + g + 8][kk + t]);
                a[mt][2] = __float_as_uint(As[r + g][kk + t + 4]);
                a[mt][3] = __float_as_uint(As[r + g + 8][kk + t + 4]);
            }
            #pragma unroll
            for (int nt = 0; nt < 8; nt++) {
                int c = wn * 64 + nt * 8;
                uint32_t b0 = __float_as_uint(Bs[c + g][kk + t]);
                uint32_t b1 = __float_as_uint(Bs[c + g][kk + t + 4]);
                #pragma unroll
                for (int mt = 0; mt < 2; mt++)
                    mma_tf32(acc[mt][nt], a[mt][0], a[mt][1], a[mt][2], a[mt][3], b0, b1);
            }
        }
    }

    // Epilogue: transpose via smem, coalesced NCHW stores with bias + residual.
    int b = row0 >> 10;
    int pixbase = row0 & 1023;
    #pragma unroll
    for (int h = 0; h < 2; h++) {
        __syncthreads();
        if (wn == h) {
            #pragma unroll
            for (int mt = 0; mt < 2; mt++) {
                int r = wm * 32 + mt * 16 + g;
                #pragma unroll
                for (int nt = 0; nt < 8; nt++) {
                    int c = nt * 8 + 2 * t;
                    Cs[r][c] = acc[mt][nt][0];
                    Cs[r][c + 1] = acc[mt][nt][1];
                    Cs[r + 8][c] = acc[mt][nt][2];
                    Cs[r + 8][c + 1] = acc[mt][nt][3];
                }
            }
        }
        __syncthreads();
        for (int idx = tid; idx < 64 * 128; idx += 256) {
            int ol = idx >> 7;
            int p = idx & 127;
            int o = col0 + h * 64 + ol;
            size_t gi = ((size_t)b * CH + o) * HWP + pixbase + p;
            out[gi] = Cs[p][ol] + bias[o] + x[gi];
        }
    }
}

// ---------------------------------------------------------------------------
extern "C" void kernel_launch(void* const* d_in, const int* in_sizes, int n_in,
                              void* d_out, int out_size) {
    const float* x      = (const float*)d_in[0];
    const float* ln_w   = (const float*)d_in[1];
    const float* ln_b   = (const float*)d_in[2];
    const float* qkv_w  = (const float*)d_in[3];
    const float* qkv_b  = (const float*)d_in[4];
    const float* proj_w = (const float*)d_in[5];
    const float* proj_b = (const float*)d_in[6];
    float* out = (float*)d_out;

    ln_kernel<<<BATCH * 32, 256>>>(x, ln_w, ln_b);
    qkv_gemm<<<dim3(12, 64), 256>>>(qkv_w, qkv_b);
    attn_kernel<<<dim3(16, NHEADS, BATCH), 128>>>();
    proj_gemm<<<dim3(4, 64), 256>>>(proj_w, proj_b, x, out);
}

// round 7
// speedup vs baseline: 2.2278x; 1.0145x over previous
#include <cuda_runtime.h>
#include <math.h>
#include <stdint.h>

#define BATCH 8
#define CH 512
#define HWP 1024
#define NHEADS 8
#define HDIM 64
#define NPIX (BATCH*HWP)   // 8192

// Scratch (allocation-free rule: __device__ globals). 128B-aligned.
__device__ alignas(128) float g_xn[(size_t)NPIX * CH];
__device__ alignas(128) float g_qkv[(size_t)NPIX * 3 * CH];
__device__ alignas(128) float g_attn[(size_t)NPIX * CH];

// ---------------------------------------------------------------------------
// Helpers
// ---------------------------------------------------------------------------
__device__ __forceinline__ uint32_t tf32u(float x) {
    uint32_t r;
    asm("cvt.rna.tf32.f32 %0, %1;" : "=r"(r) : "f"(x));
    return r;
}
__device__ __forceinline__ void mma_tf32(float* c, uint32_t a0, uint32_t a1,
                                         uint32_t a2, uint32_t a3,
                                         uint32_t b0, uint32_t b1) {
    asm volatile(
        "mma.sync.aligned.m16n8k8.row.col.f32.tf32.tf32.f32 "
        "{%0,%1,%2,%3}, {%4,%5,%6,%7}, {%8,%9}, {%0,%1,%2,%3};"
        : "+f"(c[0]), "+f"(c[1]), "+f"(c[2]), "+f"(c[3])
        : "r"(a0), "r"(a1), "r"(a2), "r"(a3), "r"(b0), "r"(b1));
}
__device__ __forceinline__ uint32_t smem_u32(const void* p) {
    return (uint32_t)__cvta_generic_to_shared(p);
}
__device__ __forceinline__ void cp16(uint32_t dst, const float* src) {
    asm volatile("cp.async.cg.shared.global [%0], [%1], 16;" :: "r"(dst), "l"(src));
}
#define CP_COMMIT() asm volatile("cp.async.commit_group;")
#define CP_WAIT(N)  asm volatile("cp.async.wait_group %0;" :: "n"(N))

// ---------------------------------------------------------------------------
// Kernel 1: LayerNorm over channels, fully coalesced R/W via smem transpose.
// Block = one (b,h) row of 32 pixels, 256 threads.
// ---------------------------------------------------------------------------
__global__ __launch_bounds__(256) void ln_kernel(const float* __restrict__ x,
                                                 const float* __restrict__ ln_w,
                                                 const float* __restrict__ ln_b) {
    int b = blockIdx.x >> 5;
    int h = blockIdx.x & 31;
    int tid = threadIdx.x;
    int w = tid & 31;
    int cg = tid >> 5;  // 0..7

    __shared__ float s_sum[8][32];
    __shared__ float s_sq[8][32];
    __shared__ float s_mean[32];
    __shared__ float s_rstd[32];
    __shared__ float s_t[32][33];

    const float* xb = x + ((size_t)b * CH) * HWP + h * 32;

    float sum = 0.f, sq = 0.f;
    for (int c = cg; c < CH; c += 8) {
        float v = xb[(size_t)c * HWP + w];
        sum += v; sq += v * v;
    }
    s_sum[cg][w] = sum;
    s_sq[cg][w] = sq;
    __syncthreads();
    if (cg == 0) {
        float ts = 0.f, tq = 0.f;
        #pragma unroll
        for (int g = 0; g < 8; g++) { ts += s_sum[g][w]; tq += s_sq[g][w]; }
        float mean = ts * (1.0f / CH);
        float var = tq * (1.0f / CH) - mean * mean;
        s_mean[w] = mean;
        s_rstd[w] = rsqrtf(var + 1e-5f);
    }
    __syncthreads();
    float mean = s_mean[w], rstd = s_rstd[w];

    size_t pixbase = (size_t)b * HWP + h * 32;
    for (int c0 = 0; c0 < CH; c0 += 32) {
        float vals[4];
        #pragma unroll
        for (int k = 0; k < 4; k++) {
            int cr = c0 + cg + k * 8;
            float v = xb[(size_t)cr * HWP + w];
            vals[k] = (v - mean) * rstd * ln_w[cr] + ln_b[cr];
        }
        __syncthreads();
        #pragma unroll
        for (int k = 0; k < 4; k++) s_t[cg + k * 8][w] = vals[k];
        __syncthreads();
        #pragma unroll
        for (int k = 0; k < 4; k++) {
            int pixl = cg + k * 8;
            g_xn[(pixbase + pixl) * CH + c0 + w] = s_t[w][pixl];
        }
    }
}

// ---------------------------------------------------------------------------
// Kernel 2: QKV GEMM (tf32 mma, cp.async 2-stage). 128x128 tile, BK=32.
// 256 threads = 8 warps (4m x 2n). smem stride 36 -> conflict-free frags.
// ---------------------------------------------------------------------------
#define PADK 36
#define GSTG (128*PADK)
__global__ __launch_bounds__(256) void qkv_gemm(const float* __restrict__ Bw,
                                                const float* __restrict__ bias) {
    extern __shared__ float dsm[];
    float* As = dsm;               // [2][128][36]
    float* Bs = dsm + 2 * GSTG;    // [2][128][36]

    int tid = threadIdx.x;
    int wid = tid >> 5, lane = tid & 31;
    int wm = wid >> 1, wn = wid & 1;
    int g = lane >> 2, t = lane & 3;
    int row0 = blockIdx.y * 128, col0 = blockIdx.x * 128;

    int lr = tid >> 1;
    int lp = (tid & 1) * 16;
    const float* Ap = g_xn + (size_t)(row0 + lr) * CH + lp;
    const float* Bp = Bw + (size_t)(col0 + lr) * CH + lp;

    float acc[2][8][4];
    #pragma unroll
    for (int mt = 0; mt < 2; mt++)
        #pragma unroll
        for (int nt = 0; nt < 8; nt++)
            #pragma unroll
            for (int j = 0; j < 4; j++) acc[mt][nt][j] = 0.f;

    uint32_t abase = smem_u32(As + lr * PADK + lp);
    uint32_t bbase = smem_u32(Bs + lr * PADK + lp);

    // prefetch stage 0
    #pragma unroll
    for (int i = 0; i < 4; i++) {
        cp16(abase + i * 16, Ap + i * 4);
        cp16(bbase + i * 16, Bp + i * 4);
    }
    CP_COMMIT();

    int s = 0;
    for (int k0 = 0; k0 < CH; k0 += 32) {
        if (k0 + 32 < CH) {
            uint32_t ao = abase + (s ^ 1) * (GSTG * 4);
            uint32_t bo = bbase + (s ^ 1) * (GSTG * 4);
            #pragma unroll
            for (int i = 0; i < 4; i++) {
                cp16(ao + i * 16, Ap + k0 + 32 + i * 4);
                cp16(bo + i * 16, Bp + k0 + 32 + i * 4);
            }
            CP_COMMIT();
            CP_WAIT(1);
        } else {
            CP_WAIT(0);
        }
        __syncthreads();
        const float* A_ = As + s * GSTG;
        const float* B_ = Bs + s * GSTG;
        #pragma unroll
        for (int ks = 0; ks < 4; ks++) {
            int kk = ks * 8;
            uint32_t a[2][4];
            #pragma unroll
            for (int mt = 0; mt < 2; mt++) {
                int r = wm * 32 + mt * 16;
                a[mt][0] = __float_as_uint(A_[(r + g) * PADK + kk + t]);
                a[mt][1] = __float_as_uint(A_[(r + g + 8) * PADK + kk + t]);
                a[mt][2] = __float_as_uint(A_[(r + g) * PADK + kk + t + 4]);
                a[mt][3] = __float_as_uint(A_[(r + g + 8) * PADK + kk + t + 4]);
            }
            #pragma unroll
            for (int nt = 0; nt < 8; nt++) {
                int c = wn * 64 + nt * 8;
                uint32_t b0 = __float_as_uint(B_[(c + g) * PADK + kk + t]);
                uint32_t b1 = __float_as_uint(B_[(c + g) * PADK + kk + t + 4]);
                #pragma unroll
                for (int mt = 0; mt < 2; mt++)
                    mma_tf32(acc[mt][nt], a[mt][0], a[mt][1], a[mt][2], a[mt][3], b0, b1);
            }
        }
        __syncthreads();
        s ^= 1;
    }

    #pragma unroll
    for (int mt = 0; mt < 2; mt++) {
        int r = row0 + wm * 32 + mt * 16 + g;
        #pragma unroll
        for (int nt = 0; nt < 8; nt++) {
            int c = col0 + wn * 64 + nt * 8 + 2 * t;
            float bx = bias[c], by = bias[c + 1];
            *(float2*)(g_qkv + (size_t)r * (3 * CH) + c) =
                make_float2(acc[mt][nt][0] + bx, acc[mt][nt][1] + by);
            *(float2*)(g_qkv + (size_t)(r + 8) * (3 * CH) + c) =
                make_float2(acc[mt][nt][2] + bx, acc[mt][nt][3] + by);
        }
    }
}

// ---------------------------------------------------------------------------
// Kernel 3: Flash attention (tf32 mma, cp.async 2-stage K/V pipeline).
// Block = (qtile64, head, b), 128 threads. Ks stride 68, Vs stride 72
// (both conflict-free for their fragment access patterns).
// ---------------------------------------------------------------------------
#define KSTRIDE 68
#define VSTRIDE 72
#define KSTG (64*KSTRIDE)
#define VSTG (64*VSTRIDE)
__global__ __launch_bounds__(128) void attn_kernel() {
    extern __shared__ float dsm[];
    float* Ks = dsm;               // [2][64][68]
    float* Vs = dsm + 2 * KSTG;    // [2][64][72]

    int tid = threadIdx.x;
    int wid = tid >> 5, lane = tid & 31;
    int g = lane >> 2, t = lane & 3;
    int b = blockIdx.z, head = blockIdx.y;
    int q0 = blockIdx.x * 64;
    int m0 = wid * 16;

    const float* base = g_qkv + (size_t)b * HWP * (3 * CH) + head * HDIM;

    int lrow = tid >> 1;           // 0..63
    int lhalf = (tid & 1) * 32;

    // Stage Q into Ks stage0 via cp.async, pull fragments to registers.
    {
        const float* qrow = base + (size_t)(q0 + lrow) * (3 * CH) + lhalf;
        uint32_t qdst = smem_u32(Ks + lrow * KSTRIDE + lhalf);
        #pragma unroll
        for (int i = 0; i < 8; i++) cp16(qdst + i * 16, qrow + i * 4);
        CP_COMMIT();
        CP_WAIT(0);
    }
    __syncthreads();
    uint32_t qf[8][4];
    #pragma unroll
    for (int ks = 0; ks < 8; ks++) {
        int kk = ks * 8;
        qf[ks][0] = __float_as_uint(Ks[(m0 + g) * KSTRIDE + kk + t]);
        qf[ks][1] = __float_as_uint(Ks[(m0 + g + 8) * KSTRIDE + kk + t]);
        qf[ks][2] = __float_as_uint(Ks[(m0 + g) * KSTRIDE + kk + t + 4]);
        qf[ks][3] = __float_as_uint(Ks[(m0 + g + 8) * KSTRIDE + kk + t + 4]);
    }
    __syncthreads();  // Q reads done before K overwrites stage0

    float oA[8][4];
    #pragma unroll
    for (int nt = 0; nt < 8; nt++)
        #pragma unroll
        for (int j = 0; j < 4; j++) oA[nt][j] = 0.f;
    float m_run0 = -INFINITY, m_run1 = -INFINITY, l0 = 0.f, l1 = 0.f;
    const float scale = 0.125f;

    // prefetch kt=0 into stage 0
    {
        const float* krow = base + CH + (size_t)lrow * (3 * CH) + lhalf;
        uint32_t kdst = smem_u32(Ks + lrow * KSTRIDE + lhalf);
        uint32_t vdst = smem_u32(Vs + lrow * VSTRIDE + lhalf);
        #pragma unroll
        for (int i = 0; i < 8; i++) {
            cp16(kdst + i * 16, krow + i * 4);
            cp16(vdst + i * 16, krow + CH + i * 4);
        }
        CP_COMMIT();
    }

    int s = 0;
    for (int kt = 0; kt < 16; kt++) {
        if (kt < 15) {
            const float* krow = base + CH + (size_t)((kt + 1) * 64 + lrow) * (3 * CH) + lhalf;
            uint32_t kdst = smem_u32(Ks + (s ^ 1) * KSTG + lrow * KSTRIDE + lhalf);
            uint32_t vdst = smem_u32(Vs + (s ^ 1) * VSTG + lrow * VSTRIDE + lhalf);
            #pragma unroll
            for (int i = 0; i < 8; i++) {
                cp16(kdst + i * 16, krow + i * 4);
                cp16(vdst + i * 16, krow + CH + i * 4);
            }
            CP_COMMIT();
            CP_WAIT(1);
        } else {
            CP_WAIT(0);
        }
        __syncthreads();
        const float* K_ = Ks + s * KSTG;
        const float* V_ = Vs + s * VSTG;

        // S = Q K^T
        float sr[8][4];
        #pragma unroll
        for (int nt = 0; nt < 8; nt++) {
            sr[nt][0] = sr[nt][1] = sr[nt][2] = sr[nt][3] = 0.f;
            #pragma unroll
            for (int ks = 0; ks < 8; ks++) {
                uint32_t b0 = __float_as_uint(K_[(nt * 8 + g) * KSTRIDE + ks * 8 + t]);
                uint32_t b1 = __float_as_uint(K_[(nt * 8 + g) * KSTRIDE + ks * 8 + t + 4]);
                mma_tf32(sr[nt], qf[ks][0], qf[ks][1], qf[ks][2], qf[ks][3], b0, b1);
            }
        }

        // Online softmax
        float sm0 = -INFINITY, sm1 = -INFINITY;
        #pragma unroll
        for (int nt = 0; nt < 8; nt++) {
            sr[nt][0] *= scale; sr[nt][1] *= scale; sr[nt][2] *= scale; sr[nt][3] *= scale;
            sm0 = fmaxf(sm0, fmaxf(sr[nt][0], sr[nt][1]));
            sm1 = fmaxf(sm1, fmaxf(sr[nt][2], sr[nt][3]));
        }
        sm0 = fmaxf(sm0, __shfl_xor_sync(0xffffffffu, sm0, 1));
        sm0 = fmaxf(sm0, __shfl_xor_sync(0xffffffffu, sm0, 2));
        sm1 = fmaxf(sm1, __shfl_xor_sync(0xffffffffu, sm1, 1));
        sm1 = fmaxf(sm1, __shfl_xor_sync(0xffffffffu, sm1, 2));
        float mn0 = fmaxf(m_run0, sm0), mn1 = fmaxf(m_run1, sm1);
        float al0 = __expf(m_run0 - mn0), al1 = __expf(m_run1 - mn1);
        float ls0 = 0.f, ls1 = 0.f;
        uint32_t pu[8][4];
        #pragma unroll
        for (int nt = 0; nt < 8; nt++) {
            float p0 = __expf(sr[nt][0] - mn0);
            float p1 = __expf(sr[nt][1] - mn0);
            float p2 = __expf(sr[nt][2] - mn1);
            float p3 = __expf(sr[nt][3] - mn1);
            ls0 += p0 + p1; ls1 += p2 + p3;
            pu[nt][0] = tf32u(p0); pu[nt][1] = tf32u(p1);
            pu[nt][2] = tf32u(p2); pu[nt][3] = tf32u(p3);
        }
        ls0 += __shfl_xor_sync(0xffffffffu, ls0, 1);
        ls0 += __shfl_xor_sync(0xffffffffu, ls0, 2);
        ls1 += __shfl_xor_sync(0xffffffffu, ls1, 1);
        ls1 += __shfl_xor_sync(0xffffffffu, ls1, 2);
        l0 = l0 * al0 + ls0; l1 = l1 * al1 + ls1;
        m_run0 = mn0; m_run1 = mn1;
        #pragma unroll
        for (int nt = 0; nt < 8; nt++) {
            oA[nt][0] *= al0; oA[nt][1] *= al0;
            oA[nt][2] *= al1; oA[nt][3] *= al1;
        }

        // P C-frag -> A-frag via shuffles, then O += P V
        int srcA = g * 4 + (t >> 1);
        int srcB = srcA + 2;
        bool odd = (t & 1);
        #pragma unroll
        for (int ks = 0; ks < 8; ks++) {
            uint32_t x0 = __shfl_sync(0xffffffffu, pu[ks][0], srcA);
            uint32_t x1 = __shfl_sync(0xffffffffu, pu[ks][1], srcA);
            uint32_t a0 = odd ? x1 : x0;
            uint32_t y0 = __shfl_sync(0xffffffffu, pu[ks][0], srcB);
            uint32_t y1 = __shfl_sync(0xffffffffu, pu[ks][1], srcB);
            uint32_t a2 = odd ? y1 : y0;
            x0 = __shfl_sync(0xffffffffu, pu[ks][2], srcA);
            x1 = __shfl_sync(0xffffffffu, pu[ks][3], srcA);
            uint32_t a1 = odd ? x1 : x0;
            y0 = __shfl_sync(0xffffffffu, pu[ks][2], srcB);
            y1 = __shfl_sync(0xffffffffu, pu[ks][3], srcB);
            uint32_t a3 = odd ? y1 : y0;
            #pragma unroll
            for (int nt = 0; nt < 8; nt++) {
                uint32_t b0 = __float_as_uint(V_[(ks * 8 + t) * VSTRIDE + nt * 8 + g]);
                uint32_t b1 = __float_as_uint(V_[(ks * 8 + t + 4) * VSTRIDE + nt * 8 + g]);
                mma_tf32(oA[nt], a0, a1, a2, a3, b0, b1);
            }
        }
        __syncthreads();
        s ^= 1;
    }

    float inv0 = 1.0f / l0, inv1 = 1.0f / l1;
    size_t r0 = (size_t)b * HWP + q0 + m0 + g;
    #pragma unroll
    for (int nt = 0; nt < 8; nt++) {
        int c = head * HDIM + nt * 8 + 2 * t;
        *(float2*)(g_attn + r0 * CH + c) =
            make_float2(oA[nt][0] * inv0, oA[nt][1] * inv0);
        *(float2*)(g_attn + (r0 + 8) * CH + c) =
            make_float2(oA[nt][2] * inv1, oA[nt][3] * inv1);
    }
}

// ---------------------------------------------------------------------------
// Kernel 4: Proj GEMM (tf32 mma, cp.async 2-stage) + bias + residual, NCHW out.
// ---------------------------------------------------------------------------
__global__ __launch_bounds__(256) void proj_gemm(const float* __restrict__ Bw,
                                                 const float* __restrict__ bias,
                                                 const float* __restrict__ x,
                                                 float* __restrict__ out) {
    extern __shared__ float dsm[];
    float* As = dsm;
    float* Bs = dsm + 2 * GSTG;
    float (*Cs)[65] = (float (*)[65])dsm;   // epilogue alias

    int tid = threadIdx.x;
    int wid = tid >> 5, lane = tid & 31;
    int wm = wid >> 1, wn = wid & 1;
    int g = lane >> 2, t = lane & 3;
    int row0 = blockIdx.y * 128, col0 = blockIdx.x * 128;

    int lr = tid >> 1;
    int lp = (tid & 1) * 16;
    const float* Ap = g_attn + (size_t)(row0 + lr) * CH + lp;
    const float* Bp = Bw + (size_t)(col0 + lr) * CH + lp;

    float acc[2][8][4];
    #pragma unroll
    for (int mt = 0; mt < 2; mt++)
        #pragma unroll
        for (int nt = 0; nt < 8; nt++)
            #pragma unroll
            for (int j = 0; j < 4; j++) acc[mt][nt][j] = 0.f;

    uint32_t abase = smem_u32(As + lr * PADK + lp);
    uint32_t bbase = smem_u32(Bs + lr * PADK + lp);

    #pragma unroll
    for (int i = 0; i < 4; i++) {
        cp16(abase + i * 16, Ap + i * 4);
        cp16(bbase + i * 16, Bp + i * 4);
    }
    CP_COMMIT();

    int s = 0;
    for (int k0 = 0; k0 < CH; k0 += 32) {
        if (k0 + 32 < CH) {
            uint32_t ao = abase + (s ^ 1) * (GSTG * 4);
            uint32_t bo = bbase + (s ^ 1) * (GSTG * 4);
            #pragma unroll
            for (int i = 0; i < 4; i++) {
                cp16(ao + i * 16, Ap + k0 + 32 + i * 4);
                cp16(bo + i * 16, Bp + k0 + 32 + i * 4);
            }
            CP_COMMIT();
            CP_WAIT(1);
        } else {
            CP_WAIT(0);
        }
        __syncthreads();
        const float* A_ = As + s * GSTG;
        const float* B_ = Bs + s * GSTG;
        #pragma unroll
        for (int ks = 0; ks < 4; ks++) {
            int kk = ks * 8;
            uint32_t a[2][4];
            #pragma unroll
            for (int mt = 0; mt < 2; mt++) {
                int r = wm * 32 + mt * 16;
                a[mt][0] = __float_as_uint(A_[(r + g) * PADK + kk + t]);
                a[mt][1] = __float_as_uint(A_[(r + g + 8) * PADK + kk + t]);
                a[mt][2] = __float_as_uint(A_[(r + g) * PADK + kk + t + 4]);
                a[mt][3] = __float_as_uint(A_[(r + g + 8) * PADK + kk + t + 4]);
            }
            #pragma unroll
            for (int nt = 0; nt < 8; nt++) {
                int c = wn * 64 + nt * 8;
                uint32_t b0 = __float_as_uint(B_[(c + g) * PADK + kk + t]);
                uint32_t b1 = __float_as_uint(B_[(c + g) * PADK + kk + t + 4]);
                #pragma unroll
                for (int mt = 0; mt < 2; mt++)
                    mma_tf32(acc[mt][nt], a[mt][0], a[mt][1], a[mt][2], a[mt][3], b0, b1);
            }
        }
        __syncthreads();
        s ^= 1;
    }

    // Epilogue: transpose via smem, coalesced NCHW stores with bias + residual.
    int b = row0 >> 10;
    int pixbase = row0 & 1023;
    #pragma unroll
    for (int h = 0; h < 2; h++) {
        __syncthreads();
        if (wn == h) {
            #pragma unroll
            for (int mt = 0; mt < 2; mt++) {
                int r = wm * 32 + mt * 16 + g;
                #pragma unroll
                for (int nt = 0; nt < 8; nt++) {
                    int c = nt * 8 + 2 * t;
                    Cs[r][c] = acc[mt][nt][0];
                    Cs[r][c + 1] = acc[mt][nt][1];
                    Cs[r + 8][c] = acc[mt][nt][2];
                    Cs[r + 8][c + 1] = acc[mt][nt][3];
                }
            }
        }
        __syncthreads();
        for (int idx = tid; idx < 64 * 128; idx += 256) {
            int ol = idx >> 7;
            int p = idx & 127;
            int o = col0 + h * 64 + ol;
            size_t gi = ((size_t)b * CH + o) * HWP + pixbase + p;
            out[gi] = Cs[p][ol] + bias[o] + x[gi];
        }
    }
}

// ---------------------------------------------------------------------------
extern "C" void kernel_launch(void* const* d_in, const int* in_sizes, int n_in,
                              void* d_out, int out_size) {
    const float* x      = (const float*)d_in[0];
    const float* ln_w   = (const float*)d_in[1];
    const float* ln_b   = (const float*)d_in[2];
    const float* qkv_w  = (const float*)d_in[3];
    const float* qkv_b  = (const float*)d_in[4];
    const float* proj_w = (const float*)d_in[5];
    const float* proj_b = (const float*)d_in[6];
    float* out = (float*)d_out;

    const int gemm_smem = 2 * 2 * GSTG * sizeof(float);           // 73728
    const int attn_smem = 2 * (KSTG + VSTG) * sizeof(float);      // 71680
    cudaFuncSetAttribute(qkv_gemm, cudaFuncAttributeMaxDynamicSharedMemorySize, gemm_smem);
    cudaFuncSetAttribute(proj_gemm, cudaFuncAttributeMaxDynamicSharedMemorySize, gemm_smem);
    cudaFuncSetAttribute(attn_kernel, cudaFuncAttributeMaxDynamicSharedMemorySize, attn_smem);

    ln_kernel<<<BATCH * 32, 256>>>(x, ln_w, ln_b);
    qkv_gemm<<<dim3(12, 64), 256, gemm_smem>>>(qkv_w, qkv_b);
    attn_kernel<<<dim3(16, NHEADS, BATCH), 128, attn_smem>>>();
    proj_gemm<<<dim3(4, 64), 256, gemm_smem>>>(proj_w, proj_b, x, out);
}